// round 2
// baseline (speedup 1.0000x reference)
#include <cuda_runtime.h>
#include <math.h>

// ---------------------------------------------------------------------------
// Problem constants
// ---------------------------------------------------------------------------
namespace {
constexpr int Bn = 64;        // graphs
constexpr int Nn = 512;       // nodes per graph
constexpr int Cc = 128;       // input channels
constexpr int Hh = 128;       // hidden
constexpr int Ed = 5;         // edge dim
constexpr int Ee = 524288;    // edges
constexpr int NT = 32768;     // total nodes
constexpr int K1 = 256;       // clusters pool 1
constexpr int K2 = 128;       // clusters pool 2

// scratch offsets (floats)
constexpr size_t O_XH   = 0;
constexpr size_t O_Q    = O_XH   + (size_t)NT*Cc;
constexpr size_t O_K    = O_Q    + (size_t)NT*Hh;
constexpr size_t O_V    = O_K    + (size_t)NT*Hh;
constexpr size_t O_SKIP = O_V    + (size_t)NT*Hh;
constexpr size_t O_AGG  = O_SKIP + (size_t)NT*Hh;
constexpr size_t O_HF   = O_AGG  + (size_t)NT*Hh;
constexpr size_t O_LOG  = O_HF   + (size_t)NT*Hh;
constexpr size_t O_AEXP = O_LOG  + (size_t)Ee;
constexpr size_t O_M    = O_AEXP + (size_t)Ee;
constexpr size_t O_DEN  = O_M    + (size_t)NT;
constexpr size_t O_SUM  = O_DEN  + (size_t)NT;
constexpr size_t O_SSQ  = O_SUM  + (size_t)Cc;
constexpr size_t O_S1   = O_SSQ  + (size_t)Cc;
constexpr size_t O_T1   = O_S1   + (size_t)NT*K1;
constexpr size_t O_OX1  = O_T1   + (size_t)NT*K1;
constexpr size_t O_OA1  = O_OX1  + (size_t)Bn*K1*Hh;
constexpr size_t O_D1   = O_OA1  + (size_t)Bn*K1*K1;
constexpr size_t O_AX1  = O_D1   + (size_t)Bn*K1;
constexpr size_t O_TMP1 = O_AX1  + (size_t)Bn*K1*Hh;
constexpr size_t O_XD2  = O_TMP1 + (size_t)Bn*K1*Hh;
constexpr size_t O_S2   = O_XD2  + (size_t)Bn*K1*Hh;
constexpr size_t O_T2   = O_S2   + (size_t)Bn*K1*K2;
constexpr size_t O_OX2  = O_T2   + (size_t)Bn*K1*K2;
constexpr size_t O_OA2  = O_OX2  + (size_t)Bn*K2*Hh;
constexpr size_t O_D2   = O_OA2  + (size_t)Bn*K2*K2;
constexpr size_t O_AX2  = O_D2   + (size_t)Bn*K2;
constexpr size_t O_TMP2 = O_AX2  + (size_t)Bn*K2*Hh;
constexpr size_t O_XD3  = O_TMP2 + (size_t)Bn*K2*Hh;
constexpr size_t O_G    = O_XD3  + (size_t)Bn*K2*Hh;
constexpr size_t O_G1   = O_G    + (size_t)Bn*Hh;
constexpr size_t TOTALF = O_G1   + (size_t)Bn*Hh;
} // namespace

__device__ float GBUF[TOTALF];

// ---------------------------------------------------------------------------
// Utility kernels
// ---------------------------------------------------------------------------
__global__ void fill_kernel(float* p, float v, size_t n) {
    size_t stride = (size_t)gridDim.x * blockDim.x;
    for (size_t i = (size_t)blockIdx.x * blockDim.x + threadIdx.x; i < n; i += stride)
        p[i] = v;
}

__device__ __forceinline__ float atomicMaxF(float* address, float val) {
    int* ai = (int*)address;
    int old = *ai;
    while (__int_as_float(old) < val) {
        int assumed = old;
        old = atomicCAS(ai, assumed, __float_as_int(val));
        if (old == assumed) break;
    }
    return __int_as_float(old);
}

// ---------------------------------------------------------------------------
// BatchNorm
// ---------------------------------------------------------------------------
__global__ void bn_reduce_kernel(const float* __restrict__ x, float* __restrict__ sum,
                                 float* __restrict__ ssq) {
    int c = threadIdx.x; // 128
    float s = 0.f, ss = 0.f;
    for (int r = blockIdx.x; r < NT; r += gridDim.x) {
        float v = x[(size_t)r * Cc + c];
        s += v; ss += v * v;
    }
    atomicAdd(&sum[c], s);
    atomicAdd(&ssq[c], ss);
}

__global__ void bn_apply_kernel(const float* __restrict__ x, const float* __restrict__ sum,
                                const float* __restrict__ ssq, const float* __restrict__ gamma,
                                const float* __restrict__ beta, float* __restrict__ xh) {
    size_t i = (size_t)blockIdx.x * blockDim.x + threadIdx.x;
    if (i >= (size_t)NT * Cc) return;
    int c = (int)(i & (Cc - 1));
    float mu  = sum[c] * (1.f / NT);
    float var = ssq[c] * (1.f / NT) - mu * mu;
    xh[i] = (x[i] - mu) * rsqrtf(var + 1e-5f) * gamma[c] + beta[c];
}

// ---------------------------------------------------------------------------
// Tiled FP32 GEMM: C[M,N] = act( op(A)*B + bias + Cadd )
//   TA=false: A is [M,K] row-major (lda=row stride)
//   TA=true : A is [K,M] row-major (lda=row stride) and we use A^T
//   B is [K,N] row-major. Requires M%64==0 (or M==64), N%64==0, K%16==0.
// ---------------------------------------------------------------------------
template <bool TA, int ACT>
__global__ void gemm_kernel(const float* __restrict__ A, const float* __restrict__ Bm,
                            float* __restrict__ C, const float* __restrict__ bias,
                            const float* __restrict__ Cadd,
                            int M, int N, int K, int lda, int ldb, int ldc,
                            long sA, long sB, long sC) {
    constexpr int BM = 64, BN = 64, BK = 16;
    __shared__ float As[BK][BM + 1];
    __shared__ float Bs[BK][BN];

    int bz = blockIdx.z;
    A  += (size_t)bz * sA;
    Bm += (size_t)bz * sB;
    C  += (size_t)bz * sC;
    const float* Cad = Cadd ? Cadd + (size_t)bz * sC : nullptr;

    int m0 = blockIdx.y * BM, n0 = blockIdx.x * BN;
    int t = threadIdx.x;
    int tx = t & 15, ty = t >> 4;

    float acc[4][4] = {};

    for (int k0 = 0; k0 < K; k0 += BK) {
        if (TA) {
            int kk = t >> 4, mm = (t & 15) << 2;
            const float4 av = *(const float4*)&A[(size_t)(k0 + kk) * lda + m0 + mm];
            As[kk][mm + 0] = av.x; As[kk][mm + 1] = av.y;
            As[kk][mm + 2] = av.z; As[kk][mm + 3] = av.w;
        } else {
            int mm = t >> 2, kk = (t & 3) << 2;
            const float4 av = *(const float4*)&A[(size_t)(m0 + mm) * lda + k0 + kk];
            As[kk + 0][mm] = av.x; As[kk + 1][mm] = av.y;
            As[kk + 2][mm] = av.z; As[kk + 3][mm] = av.w;
        }
        {
            int kk = t >> 4, nn = (t & 15) << 2;
            *(float4*)&Bs[kk][nn] = *(const float4*)&Bm[(size_t)(k0 + kk) * ldb + n0 + nn];
        }
        __syncthreads();
#pragma unroll
        for (int kk = 0; kk < BK; kk++) {
            float a0 = As[kk][ty * 4 + 0], a1 = As[kk][ty * 4 + 1];
            float a2 = As[kk][ty * 4 + 2], a3 = As[kk][ty * 4 + 3];
            float4 b = *(const float4*)&Bs[kk][tx * 4];
            acc[0][0] += a0 * b.x; acc[0][1] += a0 * b.y; acc[0][2] += a0 * b.z; acc[0][3] += a0 * b.w;
            acc[1][0] += a1 * b.x; acc[1][1] += a1 * b.y; acc[1][2] += a1 * b.z; acc[1][3] += a1 * b.w;
            acc[2][0] += a2 * b.x; acc[2][1] += a2 * b.y; acc[2][2] += a2 * b.z; acc[2][3] += a2 * b.w;
            acc[3][0] += a3 * b.x; acc[3][1] += a3 * b.y; acc[3][2] += a3 * b.z; acc[3][3] += a3 * b.w;
        }
        __syncthreads();
    }

#pragma unroll
    for (int i = 0; i < 4; i++) {
        int m = m0 + ty * 4 + i;
        size_t off = (size_t)m * ldc + n0 + tx * 4;
        float4 r = make_float4(acc[i][0], acc[i][1], acc[i][2], acc[i][3]);
        if (bias) {
            int nb = n0 + tx * 4;
            r.x += bias[nb + 0]; r.y += bias[nb + 1];
            r.z += bias[nb + 2]; r.w += bias[nb + 3];
        }
        if (Cad) {
            float4 cv = *(const float4*)&Cad[off];
            r.x += cv.x; r.y += cv.y; r.z += cv.z; r.w += cv.w;
        }
        if (ACT == 1) {
            r.x = fmaxf(r.x, 0.f); r.y = fmaxf(r.y, 0.f);
            r.z = fmaxf(r.z, 0.f); r.w = fmaxf(r.w, 0.f);
        }
        *(float4*)&C[off] = r;
    }
}

// ---------------------------------------------------------------------------
// TransformerConv edge kernels (e = edge_attr @ We computed on the fly)
// ---------------------------------------------------------------------------
__global__ void edge_logits_kernel(const int* __restrict__ src, const int* __restrict__ dst,
                                   const float* __restrict__ ea, const float* __restrict__ We,
                                   const float* __restrict__ q, const float* __restrict__ kf,
                                   float* __restrict__ logits, float* __restrict__ mmax) {
    __shared__ float sWe[Ed * Hh];
    for (int i = threadIdx.x; i < Ed * Hh; i += blockDim.x) sWe[i] = We[i];
    __syncthreads();
    int e = blockIdx.x * (blockDim.x >> 5) + (threadIdx.x >> 5);
    int lane = threadIdx.x & 31;
    if (e >= Ee) return;
    int s = src[e], d = dst[e];
    float a0 = ea[(size_t)e * 5 + 0], a1 = ea[(size_t)e * 5 + 1], a2 = ea[(size_t)e * 5 + 2];
    float a3 = ea[(size_t)e * 5 + 3], a4 = ea[(size_t)e * 5 + 4];
    float acc = 0.f;
#pragma unroll
    for (int j = 0; j < Hh / 32; j++) {
        int h = lane + 32 * j;
        float ev = a0 * sWe[h] + a1 * sWe[Hh + h] + a2 * sWe[2 * Hh + h] +
                   a3 * sWe[3 * Hh + h] + a4 * sWe[4 * Hh + h];
        acc += q[(size_t)d * Hh + h] * (kf[(size_t)s * Hh + h] + ev);
    }
#pragma unroll
    for (int o = 16; o > 0; o >>= 1) acc += __shfl_xor_sync(0xffffffffu, acc, o);
    if (lane == 0) {
        float lg = acc * 0.08838834764831845f; // 1/sqrt(128)
        logits[e] = lg;
        atomicMaxF(&mmax[d], lg);
    }
}

__global__ void edge_exp_kernel(const int* __restrict__ dst, const float* __restrict__ logits,
                                const float* __restrict__ mmax, float* __restrict__ aexp,
                                float* __restrict__ den) {
    int e = blockIdx.x * blockDim.x + threadIdx.x;
    if (e >= Ee) return;
    int d = dst[e];
    float a = __expf(logits[e] - mmax[d]);
    aexp[e] = a;
    atomicAdd(&den[d], a);
}

__global__ void edge_agg_kernel(const int* __restrict__ src, const int* __restrict__ dst,
                                const float* __restrict__ ea, const float* __restrict__ We,
                                const float* __restrict__ v, const float* __restrict__ aexp,
                                const float* __restrict__ den, float* __restrict__ agg) {
    __shared__ float sWe[Ed * Hh];
    for (int i = threadIdx.x; i < Ed * Hh; i += blockDim.x) sWe[i] = We[i];
    __syncthreads();
    int e = blockIdx.x * (blockDim.x >> 5) + (threadIdx.x >> 5);
    int lane = threadIdx.x & 31;
    if (e >= Ee) return;
    int s = src[e], d = dst[e];
    float coef = aexp[e] / den[d];
    float a0 = ea[(size_t)e * 5 + 0], a1 = ea[(size_t)e * 5 + 1], a2 = ea[(size_t)e * 5 + 2];
    float a3 = ea[(size_t)e * 5 + 3], a4 = ea[(size_t)e * 5 + 4];
#pragma unroll
    for (int j = 0; j < Hh / 32; j++) {
        int h = lane + 32 * j;
        float ev = a0 * sWe[h] + a1 * sWe[Hh + h] + a2 * sWe[2 * Hh + h] +
                   a3 * sWe[3 * Hh + h] + a4 * sWe[4 * Hh + h];
        atomicAdd(&agg[(size_t)d * Hh + h], coef * (v[(size_t)s * Hh + h] + ev));
    }
}

__global__ void add_relu_kernel(const float* __restrict__ a, const float* __restrict__ b,
                                float* __restrict__ o, size_t n) {
    size_t i = (size_t)blockIdx.x * blockDim.x + threadIdx.x;
    if (i < n) o[i] = fmaxf(a[i] + b[i], 0.f);
}

// ---------------------------------------------------------------------------
// Softmax over rows (warp per row)
// ---------------------------------------------------------------------------
__global__ void softmax_rows_kernel(float* __restrict__ X, int rows, int cols) {
    int row = blockIdx.x * (blockDim.x >> 5) + (threadIdx.x >> 5);
    int lane = threadIdx.x & 31;
    if (row >= rows) return;
    float* p = X + (size_t)row * cols;
    float mx = -1e30f;
    for (int c = lane; c < cols; c += 32) mx = fmaxf(mx, p[c]);
#pragma unroll
    for (int o = 16; o > 0; o >>= 1) mx = fmaxf(mx, __shfl_xor_sync(0xffffffffu, mx, o));
    float sum = 0.f;
    for (int c = lane; c < cols; c += 32) {
        float v = __expf(p[c] - mx);
        p[c] = v;
        sum += v;
    }
#pragma unroll
    for (int o = 16; o > 0; o >>= 1) sum += __shfl_xor_sync(0xffffffffu, sum, o);
    float inv = 1.f / sum;
    for (int c = lane; c < cols; c += 32) p[c] *= inv;
}

// ---------------------------------------------------------------------------
// Sparse T1 = adj @ s1 via edge list: T1[src,:] += s1[dst,:]
// ---------------------------------------------------------------------------
__global__ void t1_scatter_kernel(const int* __restrict__ src, const int* __restrict__ dst,
                                  const float* __restrict__ s1, float* __restrict__ T1) {
    int e = blockIdx.x * (blockDim.x >> 5) + (threadIdx.x >> 5);
    int lane = threadIdx.x & 31;
    if (e >= Ee) return;
    int s = src[e], d = dst[e];
    const float* srow = s1 + (size_t)d * K1;
    float* trow = T1 + (size_t)s * K1;
#pragma unroll
    for (int j = 0; j < K1 / 32; j++) {
        int c = lane + 32 * j;
        atomicAdd(&trow[c], srow[c]);
    }
}

// ---------------------------------------------------------------------------
// out_adj normalization: zero diag, d = sqrt(rowsum)+eps, A /= d_i d_j
// ---------------------------------------------------------------------------
__global__ void adj_rowsum_kernel(float* __restrict__ A, float* __restrict__ d, int Kd) {
    int b = blockIdx.y, i = blockIdx.x, tid = threadIdx.x;
    float* row = A + ((size_t)b * Kd + i) * Kd;
    float v = row[tid];
    if (tid == i) { v = 0.f; row[tid] = 0.f; }
    __shared__ float sh[256];
    sh[tid] = v;
    __syncthreads();
    for (int s = Kd >> 1; s > 0; s >>= 1) {
        if (tid < s) sh[tid] += sh[tid + s];
        __syncthreads();
    }
    if (tid == 0) d[(size_t)b * Kd + i] = sqrtf(sh[0]) + 1e-15f;
}

__global__ void adj_divide_kernel(float* __restrict__ A, const float* __restrict__ d, int Kd,
                                  size_t total) {
    size_t i = (size_t)blockIdx.x * blockDim.x + threadIdx.x;
    if (i >= total) return;
    int j = (int)(i % Kd);
    size_t bi = i / Kd;
    int ii = (int)(bi % Kd);
    int b = (int)(bi / Kd);
    A[i] = A[i] / (d[(size_t)b * Kd + ii] * d[(size_t)b * Kd + j]);
}

// ---------------------------------------------------------------------------
// Readout
// ---------------------------------------------------------------------------
__global__ void mean_nodes_kernel(const float* __restrict__ xd, float* __restrict__ g) {
    int b = blockIdx.x, f = threadIdx.x; // Hh threads
    float s = 0.f;
    for (int n = 0; n < K2; n++) s += xd[((size_t)b * K2 + n) * Hh + f];
    g[(size_t)b * Hh + f] = s * (1.f / K2);
}

__global__ void readout_kernel(const float* __restrict__ g1, const float* __restrict__ Wro,
                               const float* __restrict__ bro, float* __restrict__ out) {
    int b = blockIdx.x, lane = threadIdx.x;
    float s = 0.f;
    for (int j = lane; j < Hh; j += 32) s += g1[(size_t)b * Hh + j] * Wro[j];
#pragma unroll
    for (int o = 16; o > 0; o >>= 1) s += __shfl_xor_sync(0xffffffffu, s, o);
    if (lane == 0) out[b] = 1.f / (1.f + expf(-(s + bro[0])));
}

// ---------------------------------------------------------------------------
// Host side
// ---------------------------------------------------------------------------
static void launch_gemm(bool TA, int act, const float* A, const float* B, float* C,
                        const float* bias, const float* Cadd, int M, int N, int K, int lda,
                        int ldb, int ldc, long sA, long sB, long sC, int batch) {
    dim3 grid(N / 64, (M + 63) / 64, batch), block(256);
    if (TA) {
        gemm_kernel<true, 0><<<grid, block>>>(A, B, C, bias, Cadd, M, N, K, lda, ldb, ldc, sA, sB, sC);
    } else if (act == 1) {
        gemm_kernel<false, 1><<<grid, block>>>(A, B, C, bias, Cadd, M, N, K, lda, ldb, ldc, sA, sB, sC);
    } else {
        gemm_kernel<false, 0><<<grid, block>>>(A, B, C, bias, Cadd, M, N, K, lda, ldb, ldc, sA, sB, sC);
    }
}

static void fill_launch(float* p, float v, size_t n) {
    int grid = (int)((n + 255) / 256);
    if (grid > 65535) grid = 65535;
    fill_kernel<<<grid, 256>>>(p, v, n);
}

extern "C" void kernel_launch(void* const* d_in, const int* in_sizes, int n_in,
                              void* d_out, int out_size) {
    const float* x      = (const float*)d_in[0];
    const int*   ei     = (const int*)d_in[1];
    const float* ea     = (const float*)d_in[2];
    // d_in[3] = batch (unused; derived from src)
    const float* bng    = (const float*)d_in[4];
    const float* bnb    = (const float*)d_in[5];
    const float* Wq     = (const float*)d_in[6];
    const float* bq     = (const float*)d_in[7];
    const float* Wk     = (const float*)d_in[8];
    const float* bk     = (const float*)d_in[9];
    const float* Wv     = (const float*)d_in[10];
    const float* bv     = (const float*)d_in[11];
    const float* We     = (const float*)d_in[12];
    const float* Wskip  = (const float*)d_in[13];
    const float* bskip  = (const float*)d_in[14];
    const float* Wm1    = (const float*)d_in[15];
    const float* bm1    = (const float*)d_in[16];
    const float* W2rel  = (const float*)d_in[17];
    const float* b2rel  = (const float*)d_in[18];
    const float* W2root = (const float*)d_in[19];
    const float* Wm2    = (const float*)d_in[20];
    const float* bm2    = (const float*)d_in[21];
    const float* W3rel  = (const float*)d_in[22];
    const float* b3rel  = (const float*)d_in[23];
    const float* W3root = (const float*)d_in[24];
    const float* Wlin1  = (const float*)d_in[25];
    const float* blin1  = (const float*)d_in[26];
    const float* Wro    = (const float*)d_in[27];
    const float* bro    = (const float*)d_in[28];
    float* out = (float*)d_out;

    const int* src = ei;
    const int* dst = ei + Ee;

    float* gb = nullptr;
    cudaGetSymbolAddress((void**)&gb, GBUF);

    // ---- zero / init scratch that accumulates ----
    fill_launch(gb + O_SUM, 0.f, 2 * Cc);
    fill_launch(gb + O_M, -1e30f, NT);
    fill_launch(gb + O_DEN, 0.f, NT);
    fill_launch(gb + O_AGG, 0.f, (size_t)NT * Hh);
    fill_launch(gb + O_T1, 0.f, (size_t)NT * K1);

    // ---- BatchNorm ----
    bn_reduce_kernel<<<256, Cc>>>(x, gb + O_SUM, gb + O_SSQ);
    bn_apply_kernel<<<(NT * Cc) / 256, 256>>>(x, gb + O_SUM, gb + O_SSQ, bng, bnb, gb + O_XH);

    // ---- q,k,v,skip projections ----
    launch_gemm(false, 0, gb + O_XH, Wq, gb + O_Q, bq, nullptr, NT, Hh, Cc, Cc, Hh, Hh, 0, 0, 0, 1);
    launch_gemm(false, 0, gb + O_XH, Wk, gb + O_K, bk, nullptr, NT, Hh, Cc, Cc, Hh, Hh, 0, 0, 0, 1);
    launch_gemm(false, 0, gb + O_XH, Wv, gb + O_V, bv, nullptr, NT, Hh, Cc, Cc, Hh, Hh, 0, 0, 0, 1);
    launch_gemm(false, 0, gb + O_XH, Wskip, gb + O_SKIP, bskip, nullptr, NT, Hh, Cc, Cc, Hh, Hh, 0, 0, 0, 1);

    // ---- TransformerConv attention ----
    edge_logits_kernel<<<Ee / 8, 256>>>(src, dst, ea, We, gb + O_Q, gb + O_K, gb + O_LOG, gb + O_M);
    edge_exp_kernel<<<Ee / 256, 256>>>(dst, gb + O_LOG, gb + O_M, gb + O_AEXP, gb + O_DEN);
    edge_agg_kernel<<<Ee / 8, 256>>>(src, dst, ea, We, gb + O_V, gb + O_AEXP, gb + O_DEN, gb + O_AGG);
    add_relu_kernel<<<(NT * Hh) / 256, 256>>>(gb + O_AGG, gb + O_SKIP, gb + O_HF, (size_t)NT * Hh);

    // ---- pool 1: s1 = softmax(h @ Wm1 + bm1) ----
    launch_gemm(false, 0, gb + O_HF, Wm1, gb + O_S1, bm1, nullptr, NT, K1, Hh, Hh, K1, K1, 0, 0, 0, 1);
    softmax_rows_kernel<<<NT / 8, 256>>>(gb + O_S1, NT, K1);

    // T1 = adj @ s1 (sparse, via edges); ox1 = s1^T h; oa1 = s1^T T1
    t1_scatter_kernel<<<Ee / 8, 256>>>(src, dst, gb + O_S1, gb + O_T1);
    launch_gemm(true, 0, gb + O_S1, gb + O_HF, gb + O_OX1, nullptr, nullptr,
                K1, Hh, Nn, K1, Hh, Hh, (long)Nn * K1, (long)Nn * Hh, (long)K1 * Hh, Bn);
    launch_gemm(true, 0, gb + O_S1, gb + O_T1, gb + O_OA1, nullptr, nullptr,
                K1, K1, Nn, K1, K1, K1, (long)Nn * K1, (long)Nn * K1, (long)K1 * K1, Bn);

    // normalize oa1
    {
        dim3 g1(K1, Bn);
        adj_rowsum_kernel<<<g1, K1>>>(gb + O_OA1, gb + O_D1, K1);
        size_t tot = (size_t)Bn * K1 * K1;
        adj_divide_kernel<<<(int)((tot + 255) / 256), 256>>>(gb + O_OA1, gb + O_D1, K1, tot);
    }

    // ---- DenseGraphConv 2 ----
    launch_gemm(false, 0, gb + O_OA1, gb + O_OX1, gb + O_AX1, nullptr, nullptr,
                K1, Hh, K1, K1, Hh, Hh, (long)K1 * K1, (long)K1 * Hh, (long)K1 * Hh, Bn);
    launch_gemm(false, 0, gb + O_OX1, W2root, gb + O_TMP1, nullptr, nullptr,
                Bn * K1, Hh, Hh, Hh, Hh, Hh, 0, 0, 0, 1);
    launch_gemm(false, 1, gb + O_AX1, W2rel, gb + O_XD2, b2rel, gb + O_TMP1,
                Bn * K1, Hh, Hh, Hh, Hh, Hh, 0, 0, 0, 1);

    // ---- pool 2 ----
    launch_gemm(false, 0, gb + O_XD2, Wm2, gb + O_S2, bm2, nullptr,
                Bn * K1, K2, Hh, Hh, K2, K2, 0, 0, 0, 1);
    softmax_rows_kernel<<<(Bn * K1) / 8, 256>>>(gb + O_S2, Bn * K1, K2);

    launch_gemm(true, 0, gb + O_S2, gb + O_XD2, gb + O_OX2, nullptr, nullptr,
                K2, Hh, K1, K2, Hh, Hh, (long)K1 * K2, (long)K1 * Hh, (long)K2 * Hh, Bn);
    launch_gemm(false, 0, gb + O_OA1, gb + O_S2, gb + O_T2, nullptr, nullptr,
                K1, K2, K1, K1, K2, K2, (long)K1 * K1, (long)K1 * K2, (long)K1 * K2, Bn);
    launch_gemm(true, 0, gb + O_S2, gb + O_T2, gb + O_OA2, nullptr, nullptr,
                K2, K2, K1, K2, K2, K2, (long)K1 * K2, (long)K1 * K2, (long)K2 * K2, Bn);

    {
        dim3 g2(K2, Bn);
        adj_rowsum_kernel<<<g2, K2>>>(gb + O_OA2, gb + O_D2, K2);
        size_t tot = (size_t)Bn * K2 * K2;
        adj_divide_kernel<<<(int)((tot + 255) / 256), 256>>>(gb + O_OA2, gb + O_D2, K2, tot);
    }

    // ---- DenseGraphConv 3 (no relu) ----
    launch_gemm(false, 0, gb + O_OA2, gb + O_OX2, gb + O_AX2, nullptr, nullptr,
                K2, Hh, K2, K2, Hh, Hh, (long)K2 * K2, (long)K2 * Hh, (long)K2 * Hh, Bn);
    launch_gemm(false, 0, gb + O_OX2, W3root, gb + O_TMP2, nullptr, nullptr,
                Bn * K2, Hh, Hh, Hh, Hh, Hh, 0, 0, 0, 1);
    launch_gemm(false, 0, gb + O_AX2, W3rel, gb + O_XD3, b3rel, gb + O_TMP2,
                Bn * K2, Hh, Hh, Hh, Hh, Hh, 0, 0, 0, 1);

    // ---- readout ----
    mean_nodes_kernel<<<Bn, Hh>>>(gb + O_XD3, gb + O_G);
    launch_gemm(false, 1, gb + O_G, Wlin1, gb + O_G1, blin1, nullptr,
                Bn, Hh, Hh, Hh, Hh, Hh, 0, 0, 0, 1);
    readout_kernel<<<Bn, 32>>>(gb + O_G1, Wro, bro, out);
}

// round 3
// speedup vs baseline: 1.3259x; 1.3259x over previous
#include <cuda_runtime.h>
#include <math.h>

// ---------------------------------------------------------------------------
// Problem constants
// ---------------------------------------------------------------------------
namespace {
constexpr int Bn = 64;        // graphs
constexpr int Nn = 512;       // nodes per graph
constexpr int Cc = 128;       // input channels
constexpr int Hh = 128;       // hidden
constexpr int Ed = 5;         // edge dim
constexpr int Ee = 524288;    // edges
constexpr int NT = 32768;     // total nodes
constexpr int K1 = 256;       // clusters pool 1
constexpr int K2 = 128;       // clusters pool 2

// scratch offsets (floats)
constexpr size_t O_XH   = 0;
constexpr size_t O_QKVS = O_XH   + (size_t)NT*Cc;      // [NT,512] q|k|v|skip
constexpr size_t O_HF   = O_QKVS + (size_t)NT*512;
constexpr size_t O_S1   = O_HF   + (size_t)NT*Hh;
constexpr size_t O_T1   = O_S1   + (size_t)NT*K1;
constexpr size_t O_OX1  = O_T1   + (size_t)NT*K1;
constexpr size_t O_OA1  = O_OX1  + (size_t)Bn*K1*Hh;
constexpr size_t O_D1   = O_OA1  + (size_t)Bn*K1*K1;
constexpr size_t O_AX1  = O_D1   + (size_t)Bn*K1;
constexpr size_t O_TMP1 = O_AX1  + (size_t)Bn*K1*Hh;
constexpr size_t O_XD2  = O_TMP1 + (size_t)Bn*K1*Hh;
constexpr size_t O_S2   = O_XD2  + (size_t)Bn*K1*Hh;
constexpr size_t O_T2   = O_S2   + (size_t)Bn*K1*K2;
constexpr size_t O_OX2  = O_T2   + (size_t)Bn*K1*K2;
constexpr size_t O_OA2  = O_OX2  + (size_t)Bn*K2*Hh;
constexpr size_t O_D2   = O_OA2  + (size_t)Bn*K2*K2;
constexpr size_t O_AX2  = O_D2   + (size_t)Bn*K2;
constexpr size_t O_TMP2 = O_AX2  + (size_t)Bn*K2*Hh;
constexpr size_t O_XD3  = O_TMP2 + (size_t)Bn*K2*Hh;
constexpr size_t O_G    = O_XD3  + (size_t)Bn*K2*Hh;
constexpr size_t O_G1   = O_G    + (size_t)Bn*Hh;
constexpr size_t O_SUM  = O_G1   + (size_t)Bn*Hh;
constexpr size_t O_SSQ  = O_SUM  + (size_t)Cc;
constexpr size_t O_WCAT = O_SSQ  + (size_t)Cc;
constexpr size_t O_BCAT = O_WCAT + (size_t)Cc*512;
constexpr size_t O_INT  = O_BCAT + 512;               // int region starts here

// int offsets (in ints, relative to O_INT)
constexpr size_t I_ADJ  = 0;                 // dstsBySrc [Ee]
constexpr size_t I_PAIR = I_ADJ  + Ee;       // int2 pairs by dst [Ee] => 2*Ee ints
constexpr size_t I_CNTS = I_PAIR + 2*(size_t)Ee;
constexpr size_t I_CNTD = I_CNTS + NT;
constexpr size_t I_OFFS = I_CNTD + NT;
constexpr size_t I_OFFD = I_OFFS + NT + 1;
constexpr size_t I_CURS = I_OFFD + NT + 1;
constexpr size_t I_CURD = I_CURS + NT;
constexpr size_t I_END  = I_CURD + NT;

constexpr size_t TOTALF = O_INT + I_END + 64;
} // namespace

__device__ float GBUF[TOTALF];

// ---------------------------------------------------------------------------
// Utility
// ---------------------------------------------------------------------------
__global__ void fill_kernel(float* p, float v, size_t n) {
    size_t stride = (size_t)gridDim.x * blockDim.x;
    for (size_t i = (size_t)blockIdx.x * blockDim.x + threadIdx.x; i < n; i += stride)
        p[i] = v;
}

// ---------------------------------------------------------------------------
// BatchNorm
// ---------------------------------------------------------------------------
__global__ void bn_reduce_kernel(const float* __restrict__ x, float* __restrict__ sum,
                                 float* __restrict__ ssq) {
    int c = threadIdx.x; // 128
    float s = 0.f, ss = 0.f;
    for (int r = blockIdx.x; r < NT; r += gridDim.x) {
        float v = x[(size_t)r * Cc + c];
        s += v; ss += v * v;
    }
    atomicAdd(&sum[c], s);
    atomicAdd(&ssq[c], ss);
}

__global__ void bn_apply_kernel(const float* __restrict__ x, const float* __restrict__ sum,
                                const float* __restrict__ ssq, const float* __restrict__ gamma,
                                const float* __restrict__ beta, float* __restrict__ xh) {
    size_t i = (size_t)blockIdx.x * blockDim.x + threadIdx.x;
    if (i >= (size_t)NT * Cc) return;
    int c = (int)(i & (Cc - 1));
    float mu  = sum[c] * (1.f / NT);
    float var = ssq[c] * (1.f / NT) - mu * mu;
    xh[i] = (x[i] - mu) * rsqrtf(var + 1e-5f) * gamma[c] + beta[c];
}

// ---------------------------------------------------------------------------
// CSR build: counts -> scan -> scatter
// ---------------------------------------------------------------------------
__global__ void csr_count_kernel(const int* __restrict__ src, const int* __restrict__ dst,
                                 int* __restrict__ cntS, int* __restrict__ cntD) {
    int e = blockIdx.x * blockDim.x + threadIdx.x;
    if (e >= Ee) return;
    atomicAdd(&cntS[src[e]], 1);
    atomicAdd(&cntD[dst[e]], 1);
}

// one block per array (blockIdx.x: 0 -> S, 1 -> D), 1024 threads, NT = 1024*32
__global__ void csr_scan_kernel(const int* __restrict__ cntS, const int* __restrict__ cntD,
                                int* __restrict__ offS, int* __restrict__ curS,
                                int* __restrict__ offD, int* __restrict__ curD) {
    const int* cnt = blockIdx.x ? cntD : cntS;
    int* off = blockIdx.x ? offD : offS;
    int* cur = blockIdx.x ? curD : curS;
    __shared__ int sm[1024];
    int t = threadIdx.x;
    int base = t * 32;
    int s = 0;
    for (int i = 0; i < 32; i++) s += cnt[base + i];
    sm[t] = s;
    __syncthreads();
    for (int d = 1; d < 1024; d <<= 1) {
        int v = (t >= d) ? sm[t - d] : 0;
        __syncthreads();
        sm[t] += v;
        __syncthreads();
    }
    int run = sm[t] - s; // exclusive prefix of this chunk
    for (int i = 0; i < 32; i++) {
        off[base + i] = run;
        cur[base + i] = run;
        run += cnt[base + i];
    }
    if (t == 1023) off[NT] = run;
}

__global__ void csr_scatter_kernel(const int* __restrict__ src, const int* __restrict__ dst,
                                   int* __restrict__ curS, int* __restrict__ curD,
                                   int* __restrict__ dstsBySrc, int2* __restrict__ pairByDst) {
    int e = blockIdx.x * blockDim.x + threadIdx.x;
    if (e >= Ee) return;
    int s = src[e], d = dst[e];
    int ps = atomicAdd(&curS[s], 1);
    dstsBySrc[ps] = d;
    int pd = atomicAdd(&curD[d], 1);
    pairByDst[pd] = make_int2(s, e);
}

// ---------------------------------------------------------------------------
// Fused TransformerConv: warp per dst node, online softmax, + skip + relu
// qkvs layout: [NT, 512] = q(0) | k(128) | v(256) | skip(384)
// ---------------------------------------------------------------------------
__global__ void attn_fused_kernel(const int* __restrict__ offD, const int2* __restrict__ pair,
                                  const float* __restrict__ ea, const float* __restrict__ We,
                                  const float* __restrict__ qkvs, float* __restrict__ h) {
    __shared__ float sWe[Ed * Hh];
    for (int i = threadIdx.x; i < Ed * Hh; i += blockDim.x) sWe[i] = We[i];
    __syncthreads();
    int d = blockIdx.x * (blockDim.x >> 5) + (threadIdx.x >> 5);
    int lane = threadIdx.x & 31;
    if (d >= NT) return;

    float qv[4];
#pragma unroll
    for (int j = 0; j < 4; j++) qv[j] = qkvs[(size_t)d * 512 + lane + 32 * j];

    float m = -1e30f, ssum = 0.f;
    float acc[4] = {0.f, 0.f, 0.f, 0.f};

    int beg = offD[d], end = offD[d + 1];
    for (int i = beg; i < end; i++) {
        int2 p = pair[i];
        int s = p.x;
        const float* eap = ea + (size_t)p.y * 5;
        float a0 = eap[0], a1 = eap[1], a2 = eap[2], a3 = eap[3], a4 = eap[4];
        float dot = 0.f;
        float vpe[4];
#pragma unroll
        for (int j = 0; j < 4; j++) {
            int hh = lane + 32 * j;
            float ev = a0 * sWe[hh] + a1 * sWe[Hh + hh] + a2 * sWe[2 * Hh + hh] +
                       a3 * sWe[3 * Hh + hh] + a4 * sWe[4 * Hh + hh];
            float kv = qkvs[(size_t)s * 512 + 128 + hh] + ev;
            vpe[j]   = qkvs[(size_t)s * 512 + 256 + hh] + ev;
            dot += qv[j] * kv;
        }
#pragma unroll
        for (int o = 16; o > 0; o >>= 1) dot += __shfl_xor_sync(0xffffffffu, dot, o);
        float lg = dot * 0.08838834764831845f; // 1/sqrt(128)
        float mn = fmaxf(m, lg);
        float sc = __expf(m - mn);
        float pw = __expf(lg - mn);
        ssum = ssum * sc + pw;
#pragma unroll
        for (int j = 0; j < 4; j++) acc[j] = acc[j] * sc + pw * vpe[j];
        m = mn;
    }
    float inv = (ssum > 0.f) ? 1.f / ssum : 0.f;
#pragma unroll
    for (int j = 0; j < 4; j++) {
        int hh = lane + 32 * j;
        float o = acc[j] * inv + qkvs[(size_t)d * 512 + 384 + hh];
        h[(size_t)d * Hh + hh] = fmaxf(o, 0.f);
    }
}

// ---------------------------------------------------------------------------
// T1 = adj @ s1 via CSR gather: warp per src node, no atomics
// ---------------------------------------------------------------------------
__global__ void t1_gather_kernel(const int* __restrict__ offS, const int* __restrict__ dstsBySrc,
                                 const float* __restrict__ s1, float* __restrict__ T1) {
    int s = blockIdx.x * (blockDim.x >> 5) + (threadIdx.x >> 5);
    int lane = threadIdx.x & 31;
    if (s >= NT) return;
    float acc[K1 / 32] = {};
    int beg = offS[s], end = offS[s + 1];
    for (int i = beg; i < end; i++) {
        int d = dstsBySrc[i];
        const float* row = s1 + (size_t)d * K1;
#pragma unroll
        for (int j = 0; j < K1 / 32; j++) acc[j] += row[lane + 32 * j];
    }
    float* trow = T1 + (size_t)s * K1;
#pragma unroll
    for (int j = 0; j < K1 / 32; j++) trow[lane + 32 * j] = acc[j];
}

// ---------------------------------------------------------------------------
// SGEMM 128x64 tile, 8x4 micro-tile: C = act(op(A)*B + bias + Cadd)
// TA=false: A[M,K]; TA=true: A[K,M] (uses A^T). M%128==0, N%64==0, K%16==0.
// ---------------------------------------------------------------------------
template <bool TA, int ACT>
__global__ void gemm2_kernel(const float* __restrict__ A, const float* __restrict__ Bm,
                             float* __restrict__ C, const float* __restrict__ bias,
                             const float* __restrict__ Cadd,
                             int M, int N, int K, int lda, int ldb, int ldc,
                             long sA, long sB, long sC) {
    constexpr int BM = 128, BN = 64, BK = 16;
    __shared__ float As[BK][BM + 4];
    __shared__ float Bs[BK][BN];

    int bz = blockIdx.z;
    A  += (size_t)bz * sA;
    Bm += (size_t)bz * sB;
    C  += (size_t)bz * sC;
    const float* Cad = Cadd ? Cadd + (size_t)bz * sC : nullptr;

    int m0 = blockIdx.y * BM, n0 = blockIdx.x * BN;
    int t = threadIdx.x;
    int tx = t & 15, ty = t >> 4;

    float acc[8][4] = {};

    for (int k0 = 0; k0 < K; k0 += BK) {
        if (TA) {
            int kk = t >> 4, c4 = (t & 15) * 4;
#pragma unroll
            for (int r = 0; r < 2; r++) {
                int mm = c4 + r * 64;
                float4 v = *(const float4*)&A[(size_t)(k0 + kk) * lda + m0 + mm];
                *(float4*)&As[kk][mm] = v;
            }
        } else {
            int mm = t >> 1, kq = t & 1;
#pragma unroll
            for (int r = 0; r < 2; r++) {
                int kk = (kq * 2 + r) * 4;
                float4 v = *(const float4*)&A[(size_t)(m0 + mm) * lda + k0 + kk];
                As[kk + 0][mm] = v.x; As[kk + 1][mm] = v.y;
                As[kk + 2][mm] = v.z; As[kk + 3][mm] = v.w;
            }
        }
        {
            int kk = t >> 4, nn = (t & 15) * 4;
            *(float4*)&Bs[kk][nn] = *(const float4*)&Bm[(size_t)(k0 + kk) * ldb + n0 + nn];
        }
        __syncthreads();
#pragma unroll
        for (int kk = 0; kk < BK; kk++) {
            float4 a0 = *(const float4*)&As[kk][ty * 8];
            float4 a1 = *(const float4*)&As[kk][ty * 8 + 4];
            float4 b  = *(const float4*)&Bs[kk][tx * 4];
            float av[8] = {a0.x, a0.y, a0.z, a0.w, a1.x, a1.y, a1.z, a1.w};
#pragma unroll
            for (int i = 0; i < 8; i++) {
                acc[i][0] += av[i] * b.x; acc[i][1] += av[i] * b.y;
                acc[i][2] += av[i] * b.z; acc[i][3] += av[i] * b.w;
            }
        }
        __syncthreads();
    }

#pragma unroll
    for (int i = 0; i < 8; i++) {
        int m = m0 + ty * 8 + i;
        size_t off = (size_t)m * ldc + n0 + tx * 4;
        float4 r = make_float4(acc[i][0], acc[i][1], acc[i][2], acc[i][3]);
        if (bias) {
            int nb = n0 + tx * 4;
            r.x += bias[nb + 0]; r.y += bias[nb + 1];
            r.z += bias[nb + 2]; r.w += bias[nb + 3];
        }
        if (Cad) {
            float4 cv = *(const float4*)&Cad[off];
            r.x += cv.x; r.y += cv.y; r.z += cv.z; r.w += cv.w;
        }
        if (ACT == 1) {
            r.x = fmaxf(r.x, 0.f); r.y = fmaxf(r.y, 0.f);
            r.z = fmaxf(r.z, 0.f); r.w = fmaxf(r.w, 0.f);
        }
        *(float4*)&C[off] = r;
    }
}

// small 64x64 fallback (used only for M=64 readout GEMM)
template <int ACT>
__global__ void gemm64_kernel(const float* __restrict__ A, const float* __restrict__ Bm,
                              float* __restrict__ C, const float* __restrict__ bias,
                              int M, int N, int K, int lda, int ldb, int ldc) {
    constexpr int BM = 64, BN = 64, BK = 16;
    __shared__ float As[BK][BM + 1];
    __shared__ float Bs[BK][BN];
    int m0 = blockIdx.y * BM, n0 = blockIdx.x * BN;
    int t = threadIdx.x;
    int tx = t & 15, ty = t >> 4;
    float acc[4][4] = {};
    for (int k0 = 0; k0 < K; k0 += BK) {
        {
            int mm = t >> 2, kk = (t & 3) << 2;
            const float4 av = *(const float4*)&A[(size_t)(m0 + mm) * lda + k0 + kk];
            As[kk + 0][mm] = av.x; As[kk + 1][mm] = av.y;
            As[kk + 2][mm] = av.z; As[kk + 3][mm] = av.w;
        }
        {
            int kk = t >> 4, nn = (t & 15) << 2;
            *(float4*)&Bs[kk][nn] = *(const float4*)&Bm[(size_t)(k0 + kk) * ldb + n0 + nn];
        }
        __syncthreads();
#pragma unroll
        for (int kk = 0; kk < BK; kk++) {
            float a0 = As[kk][ty * 4 + 0], a1 = As[kk][ty * 4 + 1];
            float a2 = As[kk][ty * 4 + 2], a3 = As[kk][ty * 4 + 3];
            float4 b = *(const float4*)&Bs[kk][tx * 4];
            acc[0][0] += a0 * b.x; acc[0][1] += a0 * b.y; acc[0][2] += a0 * b.z; acc[0][3] += a0 * b.w;
            acc[1][0] += a1 * b.x; acc[1][1] += a1 * b.y; acc[1][2] += a1 * b.z; acc[1][3] += a1 * b.w;
            acc[2][0] += a2 * b.x; acc[2][1] += a2 * b.y; acc[2][2] += a2 * b.z; acc[2][3] += a2 * b.w;
            acc[3][0] += a3 * b.x; acc[3][1] += a3 * b.y; acc[3][2] += a3 * b.z; acc[3][3] += a3 * b.w;
        }
        __syncthreads();
    }
#pragma unroll
    for (int i = 0; i < 4; i++) {
        int m = m0 + ty * 4 + i;
        size_t off = (size_t)m * ldc + n0 + tx * 4;
        float4 r = make_float4(acc[i][0], acc[i][1], acc[i][2], acc[i][3]);
        if (bias) {
            int nb = n0 + tx * 4;
            r.x += bias[nb + 0]; r.y += bias[nb + 1];
            r.z += bias[nb + 2]; r.w += bias[nb + 3];
        }
        if (ACT == 1) {
            r.x = fmaxf(r.x, 0.f); r.y = fmaxf(r.y, 0.f);
            r.z = fmaxf(r.z, 0.f); r.w = fmaxf(r.w, 0.f);
        }
        *(float4*)&C[off] = r;
    }
}

// ---------------------------------------------------------------------------
// Weight concat for merged q|k|v|skip GEMM
// ---------------------------------------------------------------------------
__global__ void wcat_kernel(const float* __restrict__ Wq, const float* __restrict__ Wk,
                            const float* __restrict__ Wv, const float* __restrict__ Ws,
                            const float* __restrict__ bq, const float* __restrict__ bk,
                            const float* __restrict__ bv, const float* __restrict__ bs,
                            float* __restrict__ Wcat, float* __restrict__ bcat) {
    int idx = blockIdx.x * blockDim.x + threadIdx.x; // 128*512
    if (idx >= Cc * 512) return;
    int k = idx >> 9, j = idx & 511;
    int sel = j >> 7, jj = j & 127;
    const float* W = sel == 0 ? Wq : sel == 1 ? Wk : sel == 2 ? Wv : Ws;
    Wcat[idx] = W[k * Hh + jj];
    if (k == 0) {
        const float* b = sel == 0 ? bq : sel == 1 ? bk : sel == 2 ? bv : bs;
        bcat[j] = b[jj];
    }
}

// ---------------------------------------------------------------------------
// Softmax over rows (warp per row)
// ---------------------------------------------------------------------------
__global__ void softmax_rows_kernel(float* __restrict__ X, int rows, int cols) {
    int row = blockIdx.x * (blockDim.x >> 5) + (threadIdx.x >> 5);
    int lane = threadIdx.x & 31;
    if (row >= rows) return;
    float* p = X + (size_t)row * cols;
    float mx = -1e30f;
    for (int c = lane; c < cols; c += 32) mx = fmaxf(mx, p[c]);
#pragma unroll
    for (int o = 16; o > 0; o >>= 1) mx = fmaxf(mx, __shfl_xor_sync(0xffffffffu, mx, o));
    float sum = 0.f;
    for (int c = lane; c < cols; c += 32) {
        float v = __expf(p[c] - mx);
        p[c] = v;
        sum += v;
    }
#pragma unroll
    for (int o = 16; o > 0; o >>= 1) sum += __shfl_xor_sync(0xffffffffu, sum, o);
    float inv = 1.f / sum;
    for (int c = lane; c < cols; c += 32) p[c] *= inv;
}

// ---------------------------------------------------------------------------
// out_adj normalization
// ---------------------------------------------------------------------------
__global__ void adj_rowsum_kernel(float* __restrict__ A, float* __restrict__ d, int Kd) {
    int b = blockIdx.y, i = blockIdx.x, tid = threadIdx.x;
    float* row = A + ((size_t)b * Kd + i) * Kd;
    float v = row[tid];
    if (tid == i) { v = 0.f; row[tid] = 0.f; }
    __shared__ float sh[256];
    sh[tid] = v;
    __syncthreads();
    for (int s = Kd >> 1; s > 0; s >>= 1) {
        if (tid < s) sh[tid] += sh[tid + s];
        __syncthreads();
    }
    if (tid == 0) d[(size_t)b * Kd + i] = sqrtf(sh[0]) + 1e-15f;
}

__global__ void adj_divide_kernel(float* __restrict__ A, const float* __restrict__ d, int Kd,
                                  size_t total) {
    size_t i = (size_t)blockIdx.x * blockDim.x + threadIdx.x;
    if (i >= total) return;
    int j = (int)(i % Kd);
    size_t bi = i / Kd;
    int ii = (int)(bi % Kd);
    int b = (int)(bi / Kd);
    A[i] = A[i] / (d[(size_t)b * Kd + ii] * d[(size_t)b * Kd + j]);
}

// ---------------------------------------------------------------------------
// Readout
// ---------------------------------------------------------------------------
__global__ void mean_nodes_kernel(const float* __restrict__ xd, float* __restrict__ g) {
    int b = blockIdx.x, f = threadIdx.x;
    float s = 0.f;
    for (int n = 0; n < K2; n++) s += xd[((size_t)b * K2 + n) * Hh + f];
    g[(size_t)b * Hh + f] = s * (1.f / K2);
}

__global__ void readout_kernel(const float* __restrict__ g1, const float* __restrict__ Wro,
                               const float* __restrict__ bro, float* __restrict__ out) {
    int b = blockIdx.x, lane = threadIdx.x;
    float s = 0.f;
    for (int j = lane; j < Hh; j += 32) s += g1[(size_t)b * Hh + j] * Wro[j];
#pragma unroll
    for (int o = 16; o > 0; o >>= 1) s += __shfl_xor_sync(0xffffffffu, s, o);
    if (lane == 0) out[b] = 1.f / (1.f + expf(-(s + bro[0])));
}

// ---------------------------------------------------------------------------
// Host side
// ---------------------------------------------------------------------------
static void launch_gemm2(bool TA, int act, const float* A, const float* B, float* C,
                         const float* bias, const float* Cadd, int M, int N, int K, int lda,
                         int ldb, int ldc, long sA, long sB, long sC, int batch) {
    dim3 grid(N / 64, M / 128, batch), block(256);
    if (TA) {
        gemm2_kernel<true, 0><<<grid, block>>>(A, B, C, bias, Cadd, M, N, K, lda, ldb, ldc, sA, sB, sC);
    } else if (act == 1) {
        gemm2_kernel<false, 1><<<grid, block>>>(A, B, C, bias, Cadd, M, N, K, lda, ldb, ldc, sA, sB, sC);
    } else {
        gemm2_kernel<false, 0><<<grid, block>>>(A, B, C, bias, Cadd, M, N, K, lda, ldb, ldc, sA, sB, sC);
    }
}

static void fill_launch(float* p, float v, size_t n) {
    int grid = (int)((n + 255) / 256);
    if (grid > 65535) grid = 65535;
    fill_kernel<<<grid, 256>>>(p, v, n);
}

extern "C" void kernel_launch(void* const* d_in, const int* in_sizes, int n_in,
                              void* d_out, int out_size) {
    const float* x      = (const float*)d_in[0];
    const int*   ei     = (const int*)d_in[1];
    const float* ea     = (const float*)d_in[2];
    const float* bng    = (const float*)d_in[4];
    const float* bnb    = (const float*)d_in[5];
    const float* Wq     = (const float*)d_in[6];
    const float* bq     = (const float*)d_in[7];
    const float* Wk     = (const float*)d_in[8];
    const float* bk     = (const float*)d_in[9];
    const float* Wv     = (const float*)d_in[10];
    const float* bv     = (const float*)d_in[11];
    const float* We     = (const float*)d_in[12];
    const float* Wskip  = (const float*)d_in[13];
    const float* bskip  = (const float*)d_in[14];
    const float* Wm1    = (const float*)d_in[15];
    const float* bm1    = (const float*)d_in[16];
    const float* W2rel  = (const float*)d_in[17];
    const float* b2rel  = (const float*)d_in[18];
    const float* W2root = (const float*)d_in[19];
    const float* Wm2    = (const float*)d_in[20];
    const float* bm2    = (const float*)d_in[21];
    const float* W3rel  = (const float*)d_in[22];
    const float* b3rel  = (const float*)d_in[23];
    const float* W3root = (const float*)d_in[24];
    const float* Wlin1  = (const float*)d_in[25];
    const float* blin1  = (const float*)d_in[26];
    const float* Wro    = (const float*)d_in[27];
    const float* bro    = (const float*)d_in[28];
    float* out = (float*)d_out;

    const int* src = ei;
    const int* dst = ei + Ee;

    float* gb = nullptr;
    cudaGetSymbolAddress((void**)&gb, GBUF);
    int* ib = (int*)(gb + O_INT);

    int*  cntS = ib + I_CNTS;
    int*  cntD = ib + I_CNTD;
    int*  offS = ib + I_OFFS;
    int*  offD = ib + I_OFFD;
    int*  curS = ib + I_CURS;
    int*  curD = ib + I_CURD;
    int*  adjS = ib + I_ADJ;
    int2* pair = (int2*)(ib + I_PAIR);

    // ---- zero counters + bn accumulators ----
    fill_launch((float*)cntS, 0.f, 2 * (size_t)NT);   // cntS and cntD contiguous
    fill_launch(gb + O_SUM, 0.f, 2 * Cc);

    // ---- CSR build ----
    csr_count_kernel<<<Ee / 256, 256>>>(src, dst, cntS, cntD);
    csr_scan_kernel<<<2, 1024>>>(cntS, cntD, offS, curS, offD, curD);
    csr_scatter_kernel<<<Ee / 256, 256>>>(src, dst, curS, curD, adjS, pair);

    // ---- BatchNorm ----
    bn_reduce_kernel<<<256, Cc>>>(x, gb + O_SUM, gb + O_SSQ);
    bn_apply_kernel<<<(NT * Cc) / 256, 256>>>(x, gb + O_SUM, gb + O_SSQ, bng, bnb, gb + O_XH);

    // ---- merged q|k|v|skip projection ----
    wcat_kernel<<<(Cc * 512) / 256, 256>>>(Wq, Wk, Wv, Wskip, bq, bk, bv, bskip,
                                           gb + O_WCAT, gb + O_BCAT);
    launch_gemm2(false, 0, gb + O_XH, gb + O_WCAT, gb + O_QKVS, gb + O_BCAT, nullptr,
                 NT, 512, Cc, Cc, 512, 512, 0, 0, 0, 1);

    // ---- fused attention (logits + softmax + agg + skip + relu) ----
    attn_fused_kernel<<<NT / 8, 256>>>(offD, pair, ea, We, gb + O_QKVS, gb + O_HF);

    // ---- pool 1: s1 = softmax(h @ Wm1 + bm1) ----
    launch_gemm2(false, 0, gb + O_HF, Wm1, gb + O_S1, bm1, nullptr,
                 NT, K1, Hh, Hh, K1, K1, 0, 0, 0, 1);
    softmax_rows_kernel<<<NT / 8, 256>>>(gb + O_S1, NT, K1);

    // ---- T1 = adj @ s1 (CSR gather, no atomics) ----
    t1_gather_kernel<<<NT / 8, 256>>>(offS, adjS, gb + O_S1, gb + O_T1);

    // ox1 = s1^T h ; oa1 = s1^T T1 (batched, per graph)
    launch_gemm2(true, 0, gb + O_S1, gb + O_HF, gb + O_OX1, nullptr, nullptr,
                 K1, Hh, Nn, K1, Hh, Hh, (long)Nn * K1, (long)Nn * Hh, (long)K1 * Hh, Bn);
    launch_gemm2(true, 0, gb + O_S1, gb + O_T1, gb + O_OA1, nullptr, nullptr,
                 K1, K1, Nn, K1, K1, K1, (long)Nn * K1, (long)Nn * K1, (long)K1 * K1, Bn);

    // normalize oa1
    {
        dim3 g1(K1, Bn);
        adj_rowsum_kernel<<<g1, K1>>>(gb + O_OA1, gb + O_D1, K1);
        size_t tot = (size_t)Bn * K1 * K1;
        adj_divide_kernel<<<(int)((tot + 255) / 256), 256>>>(gb + O_OA1, gb + O_D1, K1, tot);
    }

    // ---- DenseGraphConv 2 ----
    launch_gemm2(false, 0, gb + O_OA1, gb + O_OX1, gb + O_AX1, nullptr, nullptr,
                 K1, Hh, K1, K1, Hh, Hh, (long)K1 * K1, (long)K1 * Hh, (long)K1 * Hh, Bn);
    launch_gemm2(false, 0, gb + O_OX1, W2root, gb + O_TMP1, nullptr, nullptr,
                 Bn * K1, Hh, Hh, Hh, Hh, Hh, 0, 0, 0, 1);
    launch_gemm2(false, 1, gb + O_AX1, W2rel, gb + O_XD2, b2rel, gb + O_TMP1,
                 Bn * K1, Hh, Hh, Hh, Hh, Hh, 0, 0, 0, 1);

    // ---- pool 2 ----
    launch_gemm2(false, 0, gb + O_XD2, Wm2, gb + O_S2, bm2, nullptr,
                 Bn * K1, K2, Hh, Hh, K2, K2, 0, 0, 0, 1);
    softmax_rows_kernel<<<(Bn * K1) / 8, 256>>>(gb + O_S2, Bn * K1, K2);

    launch_gemm2(true, 0, gb + O_S2, gb + O_XD2, gb + O_OX2, nullptr, nullptr,
                 K2, Hh, K1, K2, Hh, Hh, (long)K1 * K2, (long)K1 * Hh, (long)K2 * Hh, Bn);
    launch_gemm2(false, 0, gb + O_OA1, gb + O_S2, gb + O_T2, nullptr, nullptr,
                 K1, K2, K1, K1, K2, K2, (long)K1 * K1, (long)K1 * K2, (long)K1 * K2, Bn);
    launch_gemm2(true, 0, gb + O_S2, gb + O_T2, gb + O_OA2, nullptr, nullptr,
                 K2, K2, K1, K2, K2, K2, (long)K1 * K2, (long)K1 * K2, (long)K2 * K2, Bn);

    {
        dim3 g2(K2, Bn);
        adj_rowsum_kernel<<<g2, K2>>>(gb + O_OA2, gb + O_D2, K2);
        size_t tot = (size_t)Bn * K2 * K2;
        adj_divide_kernel<<<(int)((tot + 255) / 256), 256>>>(gb + O_OA2, gb + O_D2, K2, tot);
    }

    // ---- DenseGraphConv 3 (no relu) ----
    launch_gemm2(false, 0, gb + O_OA2, gb + O_OX2, gb + O_AX2, nullptr, nullptr,
                 K2, Hh, K2, K2, Hh, Hh, (long)K2 * K2, (long)K2 * Hh, (long)K2 * Hh, Bn);
    launch_gemm2(false, 0, gb + O_OX2, W3root, gb + O_TMP2, nullptr, nullptr,
                 Bn * K2, Hh, Hh, Hh, Hh, Hh, 0, 0, 0, 1);
    launch_gemm2(false, 0, gb + O_AX2, W3rel, gb + O_XD3, b3rel, gb + O_TMP2,
                 Bn * K2, Hh, Hh, Hh, Hh, Hh, 0, 0, 0, 1);

    // ---- readout ----
    mean_nodes_kernel<<<Bn, Hh>>>(gb + O_XD3, gb + O_G);
    gemm64_kernel<1><<<dim3(2, 1), 256>>>(gb + O_G, Wlin1, gb + O_G1, blin1,
                                          Bn, Hh, Hh, Hh, Hh, Hh);
    readout_kernel<<<Bn, 32>>>(gb + O_G1, Wro, bro, out);
}

// round 4
// speedup vs baseline: 1.4394x; 1.0856x over previous
#include <cuda_runtime.h>
#include <math.h>

// ---------------------------------------------------------------------------
// Problem constants
// ---------------------------------------------------------------------------
namespace {
constexpr int Bn = 64;        // graphs
constexpr int Nn = 512;       // nodes per graph
constexpr int Cc = 128;       // input channels
constexpr int Hh = 128;       // hidden
constexpr int Ed = 5;         // edge dim
constexpr int Ee = 524288;    // edges
constexpr int NT = 32768;     // total nodes
constexpr int K1 = 256;       // clusters pool 1
constexpr int K2 = 128;       // clusters pool 2

// scratch offsets (floats)
constexpr size_t O_XH   = 0;
constexpr size_t O_QKVS = O_XH   + (size_t)NT*Cc;      // [NT,512] q|k|v|skip
constexpr size_t O_HF   = O_QKVS + (size_t)NT*512;
constexpr size_t O_S1   = O_HF   + (size_t)NT*Hh;
constexpr size_t O_T1   = O_S1   + (size_t)NT*K1;
constexpr size_t O_OX1  = O_T1   + (size_t)NT*K1;
constexpr size_t O_OA1  = O_OX1  + (size_t)Bn*K1*Hh;
constexpr size_t O_D1   = O_OA1  + (size_t)Bn*K1*K1;
constexpr size_t O_AX1  = O_D1   + (size_t)Bn*K1;
constexpr size_t O_TMP1 = O_AX1  + (size_t)Bn*K1*Hh;
constexpr size_t O_XD2  = O_TMP1 + (size_t)Bn*K1*Hh;
constexpr size_t O_S2   = O_XD2  + (size_t)Bn*K1*Hh;
constexpr size_t O_T2   = O_S2   + (size_t)Bn*K1*K2;
constexpr size_t O_OX2  = O_T2   + (size_t)Bn*K1*K2;
constexpr size_t O_OA2  = O_OX2  + (size_t)Bn*K2*Hh;
constexpr size_t O_D2   = O_OA2  + (size_t)Bn*K2*K2;
constexpr size_t O_AX2  = O_D2   + (size_t)Bn*K2;
constexpr size_t O_TMP2 = O_AX2  + (size_t)Bn*K2*Hh;
constexpr size_t O_XD3  = O_TMP2 + (size_t)Bn*K2*Hh;
constexpr size_t O_G    = O_XD3  + (size_t)Bn*K2*Hh;
constexpr size_t O_G1   = O_G    + (size_t)Bn*Hh;
constexpr size_t O_SUM  = O_G1   + (size_t)Bn*Hh;
constexpr size_t O_SSQ  = O_SUM  + (size_t)Cc;
constexpr size_t O_WCAT = O_SSQ  + (size_t)Cc;
constexpr size_t O_BCAT = O_WCAT + (size_t)Cc*512;
constexpr size_t O_INT  = O_BCAT + 512;               // int region starts here

// int offsets (in ints, relative to O_INT)
constexpr size_t I_ADJ  = 0;                 // dstsBySrc [Ee]
constexpr size_t I_PAIR = I_ADJ  + Ee;       // int2 pairs by dst [Ee] => 2*Ee ints
constexpr size_t I_CNT  = I_PAIR + 2*(size_t)Ee;   // cntS [NT] then cntD [NT] contiguous
constexpr size_t I_OFFS = I_CNT  + 2*(size_t)NT;
constexpr size_t I_OFFD = I_OFFS + NT + 1;
constexpr size_t I_CURS = I_OFFD + NT + 1;
constexpr size_t I_CURD = I_CURS + NT;
constexpr size_t I_AUX  = I_CURD + NT;       // 256 chunk totals
constexpr size_t I_END  = I_AUX  + 256;

constexpr size_t TOTALF = O_INT + I_END + 64;
} // namespace

__device__ float GBUF[TOTALF];

// ---------------------------------------------------------------------------
// Utility
// ---------------------------------------------------------------------------
__global__ void fill_kernel(float* p, float v, size_t n) {
    size_t stride = (size_t)gridDim.x * blockDim.x;
    for (size_t i = (size_t)blockIdx.x * blockDim.x + threadIdx.x; i < n; i += stride)
        p[i] = v;
}

// ---------------------------------------------------------------------------
// BatchNorm
// ---------------------------------------------------------------------------
__global__ void bn_reduce_kernel(const float* __restrict__ x, float* __restrict__ sum,
                                 float* __restrict__ ssq) {
    int c = threadIdx.x; // 128
    float s = 0.f, ss = 0.f;
    for (int r = blockIdx.x; r < NT; r += gridDim.x) {
        float v = x[(size_t)r * Cc + c];
        s += v; ss += v * v;
    }
    atomicAdd(&sum[c], s);
    atomicAdd(&ssq[c], ss);
}

__global__ void bn_apply_kernel(const float* __restrict__ x, const float* __restrict__ sum,
                                const float* __restrict__ ssq, const float* __restrict__ gamma,
                                const float* __restrict__ beta, float* __restrict__ xh) {
    size_t i = (size_t)blockIdx.x * blockDim.x + threadIdx.x;
    if (i >= (size_t)NT * Cc) return;
    int c = (int)(i & (Cc - 1));
    float mu  = sum[c] * (1.f / NT);
    float var = ssq[c] * (1.f / NT) - mu * mu;
    xh[i] = (x[i] - mu) * rsqrtf(var + 1e-5f) * gamma[c] + beta[c];
}

// ---------------------------------------------------------------------------
// CSR build: count -> hierarchical scan -> scatter
// ---------------------------------------------------------------------------
__global__ void csr_count_kernel(const int* __restrict__ src, const int* __restrict__ dst,
                                 int* __restrict__ cnt) {
    int e = blockIdx.x * blockDim.x + threadIdx.x;
    if (e >= Ee) return;
    atomicAdd(&cnt[src[e]], 1);
    atomicAdd(&cnt[NT + dst[e]], 1);
}

// per-256-chunk scan; 256 chunks cover cnt[0..2NT)
__global__ void scan_chunk_kernel(const int* __restrict__ cnt, int* __restrict__ excl,
                                  int* __restrict__ aux) {
    __shared__ int sm[256];
    int c = blockIdx.x, t = threadIdx.x;
    int v = cnt[c * 256 + t];
    sm[t] = v;
    __syncthreads();
    for (int d = 1; d < 256; d <<= 1) {
        int u = (t >= d) ? sm[t - d] : 0;
        __syncthreads();
        sm[t] += u;
        __syncthreads();
    }
    excl[c * 256 + t] = sm[t] - v;
    if (t == 255) aux[c] = sm[255];
}

// scan aux: threads 0..127 = S half, 128..255 = D half (independent)
__global__ void scan_aux_kernel(int* __restrict__ aux) {
    __shared__ int sm[256];
    int t = threadIdx.x;
    int i = t & 127;
    int v = aux[t];
    sm[t] = v;
    __syncthreads();
    for (int d = 1; d < 128; d <<= 1) {
        int u = (i >= d) ? sm[t - d] : 0;
        __syncthreads();
        sm[t] += u;
        __syncthreads();
    }
    aux[t] = sm[t] - v; // exclusive within its half
}

// add chunk base, route to offS/offD + curS/curD; set endpoints = Ee
__global__ void scan_final_kernel(const int* __restrict__ excl, const int* __restrict__ aux,
                                  int* __restrict__ offS, int* __restrict__ curS,
                                  int* __restrict__ offD, int* __restrict__ curD) {
    int c = blockIdx.x, t = threadIdx.x;
    int idx = c * 256 + t;
    int v = excl[idx] + aux[c];
    if (idx < NT) { offS[idx] = v; curS[idx] = v; }
    else          { offD[idx - NT] = v; curD[idx - NT] = v; }
    if (idx == 0) { offS[NT] = Ee; offD[NT] = Ee; }
}

__global__ void csr_scatter_kernel(const int* __restrict__ src, const int* __restrict__ dst,
                                   int* __restrict__ curS, int* __restrict__ curD,
                                   int* __restrict__ dstsBySrc, int2* __restrict__ pairByDst) {
    int e = blockIdx.x * blockDim.x + threadIdx.x;
    if (e >= Ee) return;
    int s = src[e], d = dst[e];
    int ps = atomicAdd(&curS[s], 1);
    dstsBySrc[ps] = d;
    int pd = atomicAdd(&curD[d], 1);
    pairByDst[pd] = make_int2(s, e);
}

// ---------------------------------------------------------------------------
// Fused TransformerConv: warp per dst node, online softmax, + skip + relu
// ---------------------------------------------------------------------------
__global__ void attn_fused_kernel(const int* __restrict__ offD, const int2* __restrict__ pair,
                                  const float* __restrict__ ea, const float* __restrict__ We,
                                  const float* __restrict__ qkvs, float* __restrict__ h) {
    __shared__ float sWe[Ed * Hh];
    for (int i = threadIdx.x; i < Ed * Hh; i += blockDim.x) sWe[i] = We[i];
    __syncthreads();
    int d = blockIdx.x * (blockDim.x >> 5) + (threadIdx.x >> 5);
    int lane = threadIdx.x & 31;
    if (d >= NT) return;

    float qv[4];
#pragma unroll
    for (int j = 0; j < 4; j++) qv[j] = qkvs[(size_t)d * 512 + lane + 32 * j];

    float m = -1e30f, ssum = 0.f;
    float acc[4] = {0.f, 0.f, 0.f, 0.f};

    int beg = offD[d], end = offD[d + 1];
    for (int i = beg; i < end; i++) {
        int2 p = pair[i];
        int s = p.x;
        const float* eap = ea + (size_t)p.y * 5;
        float a0 = eap[0], a1 = eap[1], a2 = eap[2], a3 = eap[3], a4 = eap[4];
        float dot = 0.f;
        float vpe[4];
#pragma unroll
        for (int j = 0; j < 4; j++) {
            int hh = lane + 32 * j;
            float ev = a0 * sWe[hh] + a1 * sWe[Hh + hh] + a2 * sWe[2 * Hh + hh] +
                       a3 * sWe[3 * Hh + hh] + a4 * sWe[4 * Hh + hh];
            float kv = qkvs[(size_t)s * 512 + 128 + hh] + ev;
            vpe[j]   = qkvs[(size_t)s * 512 + 256 + hh] + ev;
            dot += qv[j] * kv;
        }
#pragma unroll
        for (int o = 16; o > 0; o >>= 1) dot += __shfl_xor_sync(0xffffffffu, dot, o);
        float lg = dot * 0.08838834764831845f;
        float mn = fmaxf(m, lg);
        float sc = __expf(m - mn);
        float pw = __expf(lg - mn);
        ssum = ssum * sc + pw;
#pragma unroll
        for (int j = 0; j < 4; j++) acc[j] = acc[j] * sc + pw * vpe[j];
        m = mn;
    }
    float inv = (ssum > 0.f) ? 1.f / ssum : 0.f;
#pragma unroll
    for (int j = 0; j < 4; j++) {
        int hh = lane + 32 * j;
        float o = acc[j] * inv + qkvs[(size_t)d * 512 + 384 + hh];
        h[(size_t)d * Hh + hh] = fmaxf(o, 0.f);
    }
}

// ---------------------------------------------------------------------------
// T1 = adj @ s1 via CSR gather
// ---------------------------------------------------------------------------
__global__ void t1_gather_kernel(const int* __restrict__ offS, const int* __restrict__ dstsBySrc,
                                 const float* __restrict__ s1, float* __restrict__ T1) {
    int s = blockIdx.x * (blockDim.x >> 5) + (threadIdx.x >> 5);
    int lane = threadIdx.x & 31;
    if (s >= NT) return;
    float acc[K1 / 32] = {};
    int beg = offS[s], end = offS[s + 1];
    for (int i = beg; i < end; i++) {
        int d = dstsBySrc[i];
        const float* row = s1 + (size_t)d * K1;
#pragma unroll
        for (int j = 0; j < K1 / 32; j++) acc[j] += row[lane + 32 * j];
    }
    float* trow = T1 + (size_t)s * K1;
#pragma unroll
    for (int j = 0; j < K1 / 32; j++) trow[lane + 32 * j] = acc[j];
}

// ---------------------------------------------------------------------------
// 3xTF32 tensor-core GEMM: C[M,N] = act(op(A)*B + bias + Cadd)
// BM=128, BN=64, BK=16; 8 warps (4 in M x 2 in N), warp tile 32x32.
// mma.sync.aligned.m16n8k8 tf32, fp32 accumulate, hi/lo operand split.
// ---------------------------------------------------------------------------
__device__ __forceinline__ void split_tf32(float v, unsigned& hi, unsigned& lo) {
    unsigned h;
    asm("cvt.rna.tf32.f32 %0, %1;" : "=r"(h) : "f"(v));
    float r = v - __uint_as_float(h);
    unsigned l;
    asm("cvt.rna.tf32.f32 %0, %1;" : "=r"(l) : "f"(r));
    hi = h; lo = l;
}

__device__ __forceinline__ void mma_tf32(float4& c, unsigned a0, unsigned a1, unsigned a2,
                                         unsigned a3, unsigned b0, unsigned b1) {
    asm volatile(
        "mma.sync.aligned.m16n8k8.row.col.f32.tf32.tf32.f32 "
        "{%0,%1,%2,%3}, {%4,%5,%6,%7}, {%8,%9}, {%0,%1,%2,%3};"
        : "+f"(c.x), "+f"(c.y), "+f"(c.z), "+f"(c.w)
        : "r"(a0), "r"(a1), "r"(a2), "r"(a3), "r"(b0), "r"(b1));
}

template <bool TA, int ACT>
__global__ void gemm_tf32_kernel(const float* __restrict__ A, const float* __restrict__ Bm,
                                 float* __restrict__ C, const float* __restrict__ bias,
                                 const float* __restrict__ Cadd,
                                 int M, int N, int K, int lda, int ldb, int ldc,
                                 long sA, long sB, long sC) {
    constexpr int BM = 128, BN = 64, BK = 16, LD = 20;
    __shared__ float As[BM][LD];
    __shared__ float Bs[BN][LD];

    int bz = blockIdx.z;
    A  += (size_t)bz * sA;
    Bm += (size_t)bz * sB;
    C  += (size_t)bz * sC;
    const float* Cad = Cadd ? Cadd + (size_t)bz * sC : nullptr;

    int m0 = blockIdx.y * BM, n0 = blockIdx.x * BN;
    int t = threadIdx.x;
    int warp = t >> 5, lane = t & 31;
    int wm = (warp & 3) * 32;   // warp row offset within tile
    int wn = (warp >> 2) * 32;  // warp col offset within tile

    float4 acc[2][4];
#pragma unroll
    for (int f = 0; f < 2; f++)
#pragma unroll
        for (int g = 0; g < 4; g++) acc[f][g] = make_float4(0.f, 0.f, 0.f, 0.f);

    for (int k0 = 0; k0 < K; k0 += BK) {
        // --- load A tile into As[m][k] ---
        if (!TA) {
            int m = t >> 1, kq = (t & 1) * 8;
            float4 v0 = *(const float4*)&A[(size_t)(m0 + m) * lda + k0 + kq];
            float4 v1 = *(const float4*)&A[(size_t)(m0 + m) * lda + k0 + kq + 4];
            *(float4*)&As[m][kq] = v0;
            *(float4*)&As[m][kq + 4] = v1;
        } else {
            int k = t >> 4, mb = t & 15;
            const float* arow = &A[(size_t)(k0 + k) * lda + m0];
#pragma unroll
            for (int i = 0; i < 8; i++) As[mb + 16 * i][k] = arow[mb + 16 * i];
        }
        // --- load B tile into Bs[n][k] (B is [K,N] row-major) ---
        {
            int k = t >> 4, nb = t & 15;
            const float* brow = &Bm[(size_t)(k0 + k) * ldb + n0];
#pragma unroll
            for (int i = 0; i < 4; i++) Bs[nb + 16 * i][k] = brow[nb + 16 * i];
        }
        __syncthreads();

#pragma unroll
        for (int kk = 0; kk < BK; kk += 8) {
            int rr = lane >> 2, cc = lane & 3;
            unsigned ahi[2][4], alo[2][4];
#pragma unroll
            for (int f = 0; f < 2; f++) {
                int r = wm + 16 * f + rr;
                float a0 = As[r][kk + cc];
                float a1 = As[r + 8][kk + cc];
                float a2 = As[r][kk + cc + 4];
                float a3 = As[r + 8][kk + cc + 4];
                split_tf32(a0, ahi[f][0], alo[f][0]);
                split_tf32(a1, ahi[f][1], alo[f][1]);
                split_tf32(a2, ahi[f][2], alo[f][2]);
                split_tf32(a3, ahi[f][3], alo[f][3]);
            }
            unsigned bhi[4][2], blo[4][2];
#pragma unroll
            for (int g = 0; g < 4; g++) {
                int n = wn + 8 * g + rr;
                float b0 = Bs[n][kk + cc];
                float b1 = Bs[n][kk + cc + 4];
                split_tf32(b0, bhi[g][0], blo[g][0]);
                split_tf32(b1, bhi[g][1], blo[g][1]);
            }
#pragma unroll
            for (int f = 0; f < 2; f++)
#pragma unroll
                for (int g = 0; g < 4; g++) {
                    mma_tf32(acc[f][g], ahi[f][0], ahi[f][1], ahi[f][2], ahi[f][3],
                             bhi[g][0], bhi[g][1]);
                    mma_tf32(acc[f][g], ahi[f][0], ahi[f][1], ahi[f][2], ahi[f][3],
                             blo[g][0], blo[g][1]);
                    mma_tf32(acc[f][g], alo[f][0], alo[f][1], alo[f][2], alo[f][3],
                             bhi[g][0], bhi[g][1]);
                }
        }
        __syncthreads();
    }

    // --- epilogue ---
    int rr = lane >> 2, cc = lane & 3;
#pragma unroll
    for (int f = 0; f < 2; f++) {
#pragma unroll
        for (int g = 0; g < 4; g++) {
            int r0 = m0 + wm + 16 * f + rr;
            int c0 = n0 + wn + 8 * g + cc * 2;
            float bx = 0.f, by = 0.f;
            if (bias) { bx = bias[c0]; by = bias[c0 + 1]; }
            float2 top = make_float2(acc[f][g].x + bx, acc[f][g].y + by);
            float2 bot = make_float2(acc[f][g].z + bx, acc[f][g].w + by);
            size_t offT = (size_t)r0 * ldc + c0;
            size_t offB = (size_t)(r0 + 8) * ldc + c0;
            if (Cad) {
                float2 t0 = *(const float2*)&Cad[offT];
                float2 t1 = *(const float2*)&Cad[offB];
                top.x += t0.x; top.y += t0.y;
                bot.x += t1.x; bot.y += t1.y;
            }
            if (ACT == 1) {
                top.x = fmaxf(top.x, 0.f); top.y = fmaxf(top.y, 0.f);
                bot.x = fmaxf(bot.x, 0.f); bot.y = fmaxf(bot.y, 0.f);
            }
            *(float2*)&C[offT] = top;
            *(float2*)&C[offB] = bot;
        }
    }
}

// small 64x64 FFMA GEMM for the tiny readout
template <int ACT>
__global__ void gemm64_kernel(const float* __restrict__ A, const float* __restrict__ Bm,
                              float* __restrict__ C, const float* __restrict__ bias,
                              int M, int N, int K, int lda, int ldb, int ldc) {
    constexpr int BM = 64, BN = 64, BK = 16;
    __shared__ float As[BK][BM + 1];
    __shared__ float Bs[BK][BN];
    int m0 = blockIdx.y * BM, n0 = blockIdx.x * BN;
    int t = threadIdx.x;
    int tx = t & 15, ty = t >> 4;
    float acc[4][4] = {};
    for (int k0 = 0; k0 < K; k0 += BK) {
        {
            int mm = t >> 2, kk = (t & 3) << 2;
            const float4 av = *(const float4*)&A[(size_t)(m0 + mm) * lda + k0 + kk];
            As[kk + 0][mm] = av.x; As[kk + 1][mm] = av.y;
            As[kk + 2][mm] = av.z; As[kk + 3][mm] = av.w;
        }
        {
            int kk = t >> 4, nn = (t & 15) << 2;
            *(float4*)&Bs[kk][nn] = *(const float4*)&Bm[(size_t)(k0 + kk) * ldb + n0 + nn];
        }
        __syncthreads();
#pragma unroll
        for (int kk = 0; kk < BK; kk++) {
            float a0 = As[kk][ty * 4 + 0], a1 = As[kk][ty * 4 + 1];
            float a2 = As[kk][ty * 4 + 2], a3 = As[kk][ty * 4 + 3];
            float4 b = *(const float4*)&Bs[kk][tx * 4];
            acc[0][0] += a0 * b.x; acc[0][1] += a0 * b.y; acc[0][2] += a0 * b.z; acc[0][3] += a0 * b.w;
            acc[1][0] += a1 * b.x; acc[1][1] += a1 * b.y; acc[1][2] += a1 * b.z; acc[1][3] += a1 * b.w;
            acc[2][0] += a2 * b.x; acc[2][1] += a2 * b.y; acc[2][2] += a2 * b.z; acc[2][3] += a2 * b.w;
            acc[3][0] += a3 * b.x; acc[3][1] += a3 * b.y; acc[3][2] += a3 * b.z; acc[3][3] += a3 * b.w;
        }
        __syncthreads();
    }
#pragma unroll
    for (int i = 0; i < 4; i++) {
        int m = m0 + ty * 4 + i;
        size_t off = (size_t)m * ldc + n0 + tx * 4;
        float4 r = make_float4(acc[i][0], acc[i][1], acc[i][2], acc[i][3]);
        if (bias) {
            int nb = n0 + tx * 4;
            r.x += bias[nb + 0]; r.y += bias[nb + 1];
            r.z += bias[nb + 2]; r.w += bias[nb + 3];
        }
        if (ACT == 1) {
            r.x = fmaxf(r.x, 0.f); r.y = fmaxf(r.y, 0.f);
            r.z = fmaxf(r.z, 0.f); r.w = fmaxf(r.w, 0.f);
        }
        *(float4*)&C[off] = r;
    }
}

// ---------------------------------------------------------------------------
// Weight concat for merged q|k|v|skip GEMM
// ---------------------------------------------------------------------------
__global__ void wcat_kernel(const float* __restrict__ Wq, const float* __restrict__ Wk,
                            const float* __restrict__ Wv, const float* __restrict__ Ws,
                            const float* __restrict__ bq, const float* __restrict__ bk,
                            const float* __restrict__ bv, const float* __restrict__ bs,
                            float* __restrict__ Wcat, float* __restrict__ bcat) {
    int idx = blockIdx.x * blockDim.x + threadIdx.x; // 128*512
    if (idx >= Cc * 512) return;
    int k = idx >> 9, j = idx & 511;
    int sel = j >> 7, jj = j & 127;
    const float* W = sel == 0 ? Wq : sel == 1 ? Wk : sel == 2 ? Wv : Ws;
    Wcat[idx] = W[k * Hh + jj];
    if (k == 0) {
        const float* b = sel == 0 ? bq : sel == 1 ? bk : sel == 2 ? bv : bs;
        bcat[j] = b[jj];
    }
}

// ---------------------------------------------------------------------------
// Softmax over rows
// ---------------------------------------------------------------------------
__global__ void softmax_rows_kernel(float* __restrict__ X, int rows, int cols) {
    int row = blockIdx.x * (blockDim.x >> 5) + (threadIdx.x >> 5);
    int lane = threadIdx.x & 31;
    if (row >= rows) return;
    float* p = X + (size_t)row * cols;
    float mx = -1e30f;
    for (int c = lane; c < cols; c += 32) mx = fmaxf(mx, p[c]);
#pragma unroll
    for (int o = 16; o > 0; o >>= 1) mx = fmaxf(mx, __shfl_xor_sync(0xffffffffu, mx, o));
    float sum = 0.f;
    for (int c = lane; c < cols; c += 32) {
        float v = __expf(p[c] - mx);
        p[c] = v;
        sum += v;
    }
#pragma unroll
    for (int o = 16; o > 0; o >>= 1) sum += __shfl_xor_sync(0xffffffffu, sum, o);
    float inv = 1.f / sum;
    for (int c = lane; c < cols; c += 32) p[c] *= inv;
}

// ---------------------------------------------------------------------------
// out_adj normalization
// ---------------------------------------------------------------------------
__global__ void adj_rowsum_kernel(float* __restrict__ A, float* __restrict__ d, int Kd) {
    int b = blockIdx.y, i = blockIdx.x, tid = threadIdx.x;
    float* row = A + ((size_t)b * Kd + i) * Kd;
    float v = row[tid];
    if (tid == i) { v = 0.f; row[tid] = 0.f; }
    __shared__ float sh[256];
    sh[tid] = v;
    __syncthreads();
    for (int s = Kd >> 1; s > 0; s >>= 1) {
        if (tid < s) sh[tid] += sh[tid + s];
        __syncthreads();
    }
    if (tid == 0) d[(size_t)b * Kd + i] = sqrtf(sh[0]) + 1e-15f;
}

__global__ void adj_divide_kernel(float* __restrict__ A, const float* __restrict__ d, int Kd,
                                  size_t total) {
    size_t i = (size_t)blockIdx.x * blockDim.x + threadIdx.x;
    if (i >= total) return;
    int j = (int)(i % Kd);
    size_t bi = i / Kd;
    int ii = (int)(bi % Kd);
    int b = (int)(bi / Kd);
    A[i] = A[i] / (d[(size_t)b * Kd + ii] * d[(size_t)b * Kd + j]);
}

// ---------------------------------------------------------------------------
// Readout
// ---------------------------------------------------------------------------
__global__ void mean_nodes_kernel(const float* __restrict__ xd, float* __restrict__ g) {
    int b = blockIdx.x, f = threadIdx.x;
    float s = 0.f;
    for (int n = 0; n < K2; n++) s += xd[((size_t)b * K2 + n) * Hh + f];
    g[(size_t)b * Hh + f] = s * (1.f / K2);
}

__global__ void readout_kernel(const float* __restrict__ g1, const float* __restrict__ Wro,
                               const float* __restrict__ bro, float* __restrict__ out) {
    int b = blockIdx.x, lane = threadIdx.x;
    float s = 0.f;
    for (int j = lane; j < Hh; j += 32) s += g1[(size_t)b * Hh + j] * Wro[j];
#pragma unroll
    for (int o = 16; o > 0; o >>= 1) s += __shfl_xor_sync(0xffffffffu, s, o);
    if (lane == 0) out[b] = 1.f / (1.f + expf(-(s + bro[0])));
}

// ---------------------------------------------------------------------------
// Host side
// ---------------------------------------------------------------------------
static void launch_gemm_tc(bool TA, int act, const float* A, const float* B, float* C,
                           const float* bias, const float* Cadd, int M, int N, int K, int lda,
                           int ldb, int ldc, long sA, long sB, long sC, int batch) {
    dim3 grid(N / 64, M / 128, batch), block(256);
    if (TA) {
        gemm_tf32_kernel<true, 0><<<grid, block>>>(A, B, C, bias, Cadd, M, N, K, lda, ldb, ldc, sA, sB, sC);
    } else if (act == 1) {
        gemm_tf32_kernel<false, 1><<<grid, block>>>(A, B, C, bias, Cadd, M, N, K, lda, ldb, ldc, sA, sB, sC);
    } else {
        gemm_tf32_kernel<false, 0><<<grid, block>>>(A, B, C, bias, Cadd, M, N, K, lda, ldb, ldc, sA, sB, sC);
    }
}

static void fill_launch(float* p, float v, size_t n) {
    int grid = (int)((n + 255) / 256);
    if (grid > 65535) grid = 65535;
    fill_kernel<<<grid, 256>>>(p, v, n);
}

extern "C" void kernel_launch(void* const* d_in, const int* in_sizes, int n_in,
                              void* d_out, int out_size) {
    const float* x      = (const float*)d_in[0];
    const int*   ei     = (const int*)d_in[1];
    const float* ea     = (const float*)d_in[2];
    const float* bng    = (const float*)d_in[4];
    const float* bnb    = (const float*)d_in[5];
    const float* Wq     = (const float*)d_in[6];
    const float* bq     = (const float*)d_in[7];
    const float* Wk     = (const float*)d_in[8];
    const float* bk     = (const float*)d_in[9];
    const float* Wv     = (const float*)d_in[10];
    const float* bv     = (const float*)d_in[11];
    const float* We     = (const float*)d_in[12];
    const float* Wskip  = (const float*)d_in[13];
    const float* bskip  = (const float*)d_in[14];
    const float* Wm1    = (const float*)d_in[15];
    const float* bm1    = (const float*)d_in[16];
    const float* W2rel  = (const float*)d_in[17];
    const float* b2rel  = (const float*)d_in[18];
    const float* W2root = (const float*)d_in[19];
    const float* Wm2    = (const float*)d_in[20];
    const float* bm2    = (const float*)d_in[21];
    const float* W3rel  = (const float*)d_in[22];
    const float* b3rel  = (const float*)d_in[23];
    const float* W3root = (const float*)d_in[24];
    const float* Wlin1  = (const float*)d_in[25];
    const float* blin1  = (const float*)d_in[26];
    const float* Wro    = (const float*)d_in[27];
    const float* bro    = (const float*)d_in[28];
    float* out = (float*)d_out;

    const int* src = ei;
    const int* dst = ei + Ee;

    float* gb = nullptr;
    cudaGetSymbolAddress((void**)&gb, GBUF);
    int* ib = (int*)(gb + O_INT);

    int*  cnt  = ib + I_CNT;
    int*  offS = ib + I_OFFS;
    int*  offD = ib + I_OFFD;
    int*  curS = ib + I_CURS;
    int*  curD = ib + I_CURD;
    int*  aux  = ib + I_AUX;
    int*  adjS = ib + I_ADJ;
    int2* pair = (int2*)(ib + I_PAIR);

    // ---- zero counters + bn accumulators ----
    fill_launch((float*)cnt, 0.f, 2 * (size_t)NT);
    fill_launch(gb + O_SUM, 0.f, 2 * Cc);

    // ---- CSR build (hierarchical scan) ----
    csr_count_kernel<<<Ee / 256, 256>>>(src, dst, cnt);
    scan_chunk_kernel<<<256, 256>>>(cnt, ib + I_CURS /*reuse as excl scratch? no*/, aux);
    // NOTE: excl scratch must not alias curS; use cnt itself as excl output is fine
    // (we rewrite it below) — but cnt is needed? After chunk scan we don't need cnt.
    // We wrote excl into curS region above which is [2*NT] spanning curS+curD: OK since
    // they are exactly 2*NT contiguous ints and get overwritten by scan_final.
    scan_aux_kernel<<<1, 256>>>(aux);
    scan_final_kernel<<<256, 256>>>(ib + I_CURS, aux, offS, curS, offD, curD);
    csr_scatter_kernel<<<Ee / 256, 256>>>(src, dst, curS, curD, adjS, pair);

    // ---- BatchNorm ----
    bn_reduce_kernel<<<256, Cc>>>(x, gb + O_SUM, gb + O_SSQ);
    bn_apply_kernel<<<(NT * Cc) / 256, 256>>>(x, gb + O_SUM, gb + O_SSQ, bng, bnb, gb + O_XH);

    // ---- merged q|k|v|skip projection ----
    wcat_kernel<<<(Cc * 512) / 256, 256>>>(Wq, Wk, Wv, Wskip, bq, bk, bv, bskip,
                                           gb + O_WCAT, gb + O_BCAT);
    launch_gemm_tc(false, 0, gb + O_XH, gb + O_WCAT, gb + O_QKVS, gb + O_BCAT, nullptr,
                   NT, 512, Cc, Cc, 512, 512, 0, 0, 0, 1);

    // ---- fused attention ----
    attn_fused_kernel<<<NT / 8, 256>>>(offD, pair, ea, We, gb + O_QKVS, gb + O_HF);

    // ---- pool 1 ----
    launch_gemm_tc(false, 0, gb + O_HF, Wm1, gb + O_S1, bm1, nullptr,
                   NT, K1, Hh, Hh, K1, K1, 0, 0, 0, 1);
    softmax_rows_kernel<<<NT / 8, 256>>>(gb + O_S1, NT, K1);

    t1_gather_kernel<<<NT / 8, 256>>>(offS, adjS, gb + O_S1, gb + O_T1);

    launch_gemm_tc(true, 0, gb + O_S1, gb + O_HF, gb + O_OX1, nullptr, nullptr,
                   K1, Hh, Nn, K1, Hh, Hh, (long)Nn * K1, (long)Nn * Hh, (long)K1 * Hh, Bn);
    launch_gemm_tc(true, 0, gb + O_S1, gb + O_T1, gb + O_OA1, nullptr, nullptr,
                   K1, K1, Nn, K1, K1, K1, (long)Nn * K1, (long)Nn * K1, (long)K1 * K1, Bn);

    {
        dim3 g1(K1, Bn);
        adj_rowsum_kernel<<<g1, K1>>>(gb + O_OA1, gb + O_D1, K1);
        size_t tot = (size_t)Bn * K1 * K1;
        adj_divide_kernel<<<(int)((tot + 255) / 256), 256>>>(gb + O_OA1, gb + O_D1, K1, tot);
    }

    // ---- DenseGraphConv 2 ----
    launch_gemm_tc(false, 0, gb + O_OA1, gb + O_OX1, gb + O_AX1, nullptr, nullptr,
                   K1, Hh, K1, K1, Hh, Hh, (long)K1 * K1, (long)K1 * Hh, (long)K1 * Hh, Bn);
    launch_gemm_tc(false, 0, gb + O_OX1, W2root, gb + O_TMP1, nullptr, nullptr,
                   Bn * K1, Hh, Hh, Hh, Hh, Hh, 0, 0, 0, 1);
    launch_gemm_tc(false, 1, gb + O_AX1, W2rel, gb + O_XD2, b2rel, gb + O_TMP1,
                   Bn * K1, Hh, Hh, Hh, Hh, Hh, 0, 0, 0, 1);

    // ---- pool 2 ----
    launch_gemm_tc(false, 0, gb + O_XD2, Wm2, gb + O_S2, bm2, nullptr,
                   Bn * K1, K2, Hh, Hh, K2, K2, 0, 0, 0, 1);
    softmax_rows_kernel<<<(Bn * K1) / 8, 256>>>(gb + O_S2, Bn * K1, K2);

    launch_gemm_tc(true, 0, gb + O_S2, gb + O_XD2, gb + O_OX2, nullptr, nullptr,
                   K2, Hh, K1, K2, Hh, Hh, (long)K1 * K2, (long)K1 * Hh, (long)K2 * Hh, Bn);
    launch_gemm_tc(false, 0, gb + O_OA1, gb + O_S2, gb + O_T2, nullptr, nullptr,
                   K1, K2, K1, K1, K2, K2, (long)K1 * K1, (long)K1 * K2, (long)K1 * K2, Bn);
    launch_gemm_tc(true, 0, gb + O_S2, gb + O_T2, gb + O_OA2, nullptr, nullptr,
                   K2, K2, K1, K2, K2, K2, (long)K1 * K2, (long)K1 * K2, (long)K2 * K2, Bn);

    {
        dim3 g2(K2, Bn);
        adj_rowsum_kernel<<<g2, K2>>>(gb + O_OA2, gb + O_D2, K2);
        size_t tot = (size_t)Bn * K2 * K2;
        adj_divide_kernel<<<(int)((tot + 255) / 256), 256>>>(gb + O_OA2, gb + O_D2, K2, tot);
    }

    // ---- DenseGraphConv 3 ----
    launch_gemm_tc(false, 0, gb + O_OA2, gb + O_OX2, gb + O_AX2, nullptr, nullptr,
                   K2, Hh, K2, K2, Hh, Hh, (long)K2 * K2, (long)K2 * Hh, (long)K2 * Hh, Bn);
    launch_gemm_tc(false, 0, gb + O_OX2, W3root, gb + O_TMP2, nullptr, nullptr,
                   Bn * K2, Hh, Hh, Hh, Hh, Hh, 0, 0, 0, 1);
    launch_gemm_tc(false, 0, gb + O_AX2, W3rel, gb + O_XD3, b3rel, gb + O_TMP2,
                   Bn * K2, Hh, Hh, Hh, Hh, Hh, 0, 0, 0, 1);

    // ---- readout ----
    mean_nodes_kernel<<<Bn, Hh>>>(gb + O_XD3, gb + O_G);
    gemm64_kernel<1><<<dim3(2, 1), 256>>>(gb + O_G, Wlin1, gb + O_G1, blin1,
                                          Bn, Hh, Hh, Hh, Hh, Hh);
    readout_kernel<<<Bn, 32>>>(gb + O_G1, Wro, bro, out);
}